// round 16
// baseline (speedup 1.0000x reference)
#include <cuda_runtime.h>
#include <math.h>

#define B_    8
#define T_    2048
#define L0_   2044          // conv-window output length
#define L_    2045          // after cls token
#define NR    (B_*L_)       // 16360 rows
#define DIM   128
#define DIN   256
#define NHEAD 4
#define PDIM  64
#define NSTATE 64
#define CD    384           // conv_dim
#define DPJ   644           // d_in_proj
#define DEPTH 4
#define SCHUNK 16
#define CS     128          // scan chunk size (sequential steps per block)
#define NCHUNK 16           // ceil(2045/128)

// ---------------- scratch (static device globals; no runtime allocation) -----
__device__ float g_h [NR*DIM];               // hidden (B,L,128)
__device__ float g_zx[(size_t)NR*DPJ];       // zxbcdt (B,L,644)
__device__ float g_xc[(size_t)NR*CD];        // conv+silu output (B,L,384)
__device__ float g_dt[NR*NHEAD];             // softplus(dt) (B,L,4)
__device__ float g_yp[2][(size_t)NR*DIN];    // y partials (2 n-halves)
__device__ float g_y [(size_t)NR*DIN];       // normalized y (B,L,256)
__device__ float g_cd[B_*NHEAD*L_];          // within-chunk cumulative decay P_t
__device__ float g_st[(size_t)1024*256*8];   // chunk-end states per scan1 block
__device__ float g_carry[(size_t)1024*256*8];// carry-in states per chunk

// ---------------- frontend: sliding window -> MLP -> h; also write cls row ---
__global__ void k_frontend(const float* __restrict__ x,
                           const float* __restrict__ w1, const float* __restrict__ b1,
                           const float* __restrict__ w2, const float* __restrict__ b2,
                           const float* __restrict__ cls)
{
    int b = blockIdx.y;
    int t = threadIdx.x;              // 128
    __shared__ float toks[16];
    __shared__ float h1s[128];

    if (blockIdx.x == 0) {
        g_h[(size_t)(b*L_ + (L_-1))*DIM + t] = cls[t];
    }
    for (int r = 0; r < 8; ++r) {
        int l = blockIdx.x*8 + r;
        if (l >= L0_) break;
        if (t < 15) toks[t] = x[(size_t)(b*T_ + l + t/3)*3 + (t%3)];
        __syncthreads();
        float a = b1[t];
        #pragma unroll
        for (int j = 0; j < 15; j++) a = fmaf(toks[j], w1[t*15 + j], a);
        a = 0.5f*a*(1.0f + erff(a*0.70710678118654752f));
        h1s[t] = a;
        __syncthreads();
        float o = b2[t];
        #pragma unroll 8
        for (int j = 0; j < 128; j++) o = fmaf(h1s[j], w2[t*128 + j], o);
        g_h[(size_t)(b*L_ + l)*DIM + t] = o;
        __syncthreads();
    }
}

// ---------------- generic SGEMM: C[M,N] = A[M,K] @ W[N,K]^T ------------------
__global__ void k_gemm(const float* __restrict__ A, const float* __restrict__ W,
                       float* __restrict__ C, int M, int N, int K)
{
    __shared__ float As[64][68];
    __shared__ float Bs[64][68];
    int tid = threadIdx.x;
    int tx = tid & 15, ty = tid >> 4;
    int bm = blockIdx.x * 64, bn = blockIdx.y * 64;
    float acc[4][4] = {};
    int lr = tid >> 2;
    int lk = (tid & 3) * 16;

    for (int kb = 0; kb < K; kb += 64) {
        {
            int gr = bm + lr;
            const float* ap = A + (size_t)gr*K + kb + lk;
            #pragma unroll
            for (int i = 0; i < 16; i += 4) {
                float4 v = (gr < M) ? *(const float4*)(ap + i) : make_float4(0,0,0,0);
                As[lk+i+0][lr] = v.x; As[lk+i+1][lr] = v.y;
                As[lk+i+2][lr] = v.z; As[lk+i+3][lr] = v.w;
            }
            int gc = bn + lr;
            const float* wp = W + (size_t)gc*K + kb + lk;
            #pragma unroll
            for (int i = 0; i < 16; i += 4) {
                float4 v = (gc < N) ? *(const float4*)(wp + i) : make_float4(0,0,0,0);
                Bs[lk+i+0][lr] = v.x; Bs[lk+i+1][lr] = v.y;
                Bs[lk+i+2][lr] = v.z; Bs[lk+i+3][lr] = v.w;
            }
        }
        __syncthreads();
        #pragma unroll 16
        for (int kk = 0; kk < 64; ++kk) {
            float4 a  = *(const float4*)&As[kk][ty*4];
            float4 bv = *(const float4*)&Bs[kk][tx*4];
            float av[4] = {a.x, a.y, a.z, a.w};
            float bw[4] = {bv.x, bv.y, bv.z, bv.w};
            #pragma unroll
            for (int i = 0; i < 4; i++)
                #pragma unroll
                for (int j = 0; j < 4; j++)
                    acc[i][j] = fmaf(av[i], bw[j], acc[i][j]);
        }
        __syncthreads();
    }
    #pragma unroll
    for (int i = 0; i < 4; i++) {
        int r = bm + ty*4 + i;
        if (r < M) {
            #pragma unroll
            for (int j = 0; j < 4; j++) {
                int c = bn + tx*4 + j;
                if (c < N) C[(size_t)r*N + c] = acc[i][j];
            }
        }
    }
}

// ---------------- causal depthwise conv (K=4) + SiLU, and softplus(dt) ------
__global__ void k_convdt(const float* __restrict__ cw, const float* __restrict__ cb,
                         const float* __restrict__ dtb, int layer)
{
    int row = blockIdx.x;
    int b = row / L_;
    int l = row - b*L_;
    int t = threadIdx.x;   // 128
    #pragma unroll
    for (int rep = 0; rep < 3; rep++) {
        int c = t + rep*128;
        float4 w = *(const float4*)(cw + ((size_t)layer*CD + c)*4);
        float wv[4] = {w.x, w.y, w.z, w.w};
        float acc = cb[layer*CD + c];
        #pragma unroll
        for (int k = 0; k < 4; k++) {
            int tt = l - 3 + k;
            if (tt >= 0)
                acc = fmaf(wv[k], g_zx[((size_t)(b*L_ + tt))*DPJ + DIN + c], acc);
        }
        acc = acc / (1.0f + __expf(-acc));   // SiLU
        g_xc[(size_t)row*CD + c] = acc;
    }
    if (t < NHEAD) {
        float raw = g_zx[(size_t)row*DPJ + 640 + t] + dtb[layer*NHEAD + t];
        float sp  = (raw > 20.0f) ? raw : log1pf(__expf(raw));
        g_dt[row*NHEAD + t] = sp;
    }
}

// ---------------- chunked SSM scan: pass 1 (local scan, h=0 start) ----------
// grid = 1024: blk = ((b*4+head)*2+nh)*16 + chunk. 256 threads:
//   warp w, lane l: p = (w&1)*32 + l ; nchunk = w>>2? no: w>>1 (8 n per thread)
__global__ void k_scan1(const float* __restrict__ A_log, int layer)
{
    __shared__ float in_s[SCHUNK][128];   // per step: x[64] | B[32] | C[32]
    __shared__ float dts[SCHUNK];
    __shared__ float yp[SCHUNK*4*64];     // [step][nchunk][p]

    int blk   = blockIdx.x;
    int chunk = blk & 15;
    int grp   = blk >> 4;                 // 0..63
    int nh    =  grp       & 1;
    int head  = (grp >> 1) & 3;
    int b     =  grp >> 3;
    float A   = -__expf(A_log[layer*NHEAD + head]);

    int c0   = chunk * CS;
    int cend = (c0 + CS < L_) ? (c0 + CS) : L_;

    int tid  = threadIdx.x;
    int w    = tid >> 5, lane = tid & 31;
    int p    = ((w & 1) << 5) + lane;
    int nchunk = w >> 1;

    float s[8];
    #pragma unroll
    for (int j = 0; j < 8; j++) s[j] = 0.0f;
    float cp = 1.0f;                      // cumulative decay within chunk
    int   cdb = (b*NHEAD + head)*L_;
    bool  wr_cd = (tid == 0) && (nh == 0);

    // cooperative-load mapping: 16 threads per step, 8 floats each
    int lls = tid >> 4;
    int j0  = (tid & 15) * 8;
    int goff;
    if (j0 < 64)      goff = head*64 + j0;
    else if (j0 < 96) goff = 256 + nh*32 + (j0 - 64);
    else              goff = 320 + nh*32 + (j0 - 96);

    int rls = tid >> 4;
    int rp4 = (tid & 15) << 2;
    float* ypbase = &g_yp[nh][0];

    for (int l0 = c0; l0 < cend; l0 += SCHUNK) {
        {
            int ll = l0 + lls;
            float4 v0, v1;
            if (ll < L_) {
                const float* rp = g_xc + (size_t)(b*L_ + ll)*CD + goff;
                v0 = *(const float4*)rp;
                v1 = *(const float4*)(rp + 4);
            } else {
                v0 = make_float4(0,0,0,0); v1 = v0;
            }
            *(float4*)&in_s[lls][j0]     = v0;
            *(float4*)&in_s[lls][j0 + 4] = v1;
            if (tid < SCHUNK) {
                int l2 = l0 + tid;
                dts[tid] = (l2 < L_) ? g_dt[(b*L_ + l2)*NHEAD + head] : 0.0f;
            }
        }
        __syncthreads();

        int smax = (cend - l0 < SCHUNK) ? (cend - l0) : SCHUNK;
        for (int ls = 0; ls < smax; ++ls) {
            float dtv   = dts[ls];
            float decay = __expf(dtv * A);
            cp *= decay;
            if (wr_cd) g_cd[cdb + l0 + ls] = cp;
            float dtx   = dtv * in_s[ls][p];
            const float* bp = &in_s[ls][64 + (nchunk << 3)];
            const float* cc = &in_s[ls][96 + (nchunk << 3)];
            float4 b0 = *(const float4*)bp,  b1 = *(const float4*)(bp + 4);
            float4 cv0 = *(const float4*)cc, cv1 = *(const float4*)(cc + 4);
            float acc;
            s[0] = fmaf(s[0], decay, dtx*b0.x); acc = s[0]*cv0.x;
            s[1] = fmaf(s[1], decay, dtx*b0.y); acc = fmaf(s[1], cv0.y, acc);
            s[2] = fmaf(s[2], decay, dtx*b0.z); acc = fmaf(s[2], cv0.z, acc);
            s[3] = fmaf(s[3], decay, dtx*b0.w); acc = fmaf(s[3], cv0.w, acc);
            s[4] = fmaf(s[4], decay, dtx*b1.x); acc = fmaf(s[4], cv1.x, acc);
            s[5] = fmaf(s[5], decay, dtx*b1.y); acc = fmaf(s[5], cv1.y, acc);
            s[6] = fmaf(s[6], decay, dtx*b1.z); acc = fmaf(s[6], cv1.z, acc);
            s[7] = fmaf(s[7], decay, dtx*b1.w); acc = fmaf(s[7], cv1.w, acc);
            yp[((ls << 2) + nchunk)*64 + p] = acc;
        }
        __syncthreads();

        if (l0 + rls < cend) {
            const float* y0 = &yp[(rls << 2)*64 + rp4];
            float4 a0 = *(const float4*)(y0);
            float4 a1 = *(const float4*)(y0 + 64);
            float4 a2 = *(const float4*)(y0 + 128);
            float4 a3 = *(const float4*)(y0 + 192);
            float4 r;
            r.x = a0.x + a1.x + a2.x + a3.x;
            r.y = a0.y + a1.y + a2.y + a3.y;
            r.z = a0.z + a1.z + a2.z + a3.z;
            r.w = a0.w + a1.w + a2.w + a3.w;
            *(float4*)(ypbase + (size_t)(b*L_ + l0 + rls)*DIN + head*64 + rp4) = r;
        }
        __syncthreads();
    }

    // store chunk-end state
    size_t sb = ((size_t)blk*256 + tid)*8;
    *(float4*)&g_st[sb]     = make_float4(s[0], s[1], s[2], s[3]);
    *(float4*)&g_st[sb + 4] = make_float4(s[4], s[5], s[6], s[7]);
}

// ---------------- pass 2: sequential chunk-carry fix-up (tiny) --------------
__global__ void k_fix(int layer)
{
    int grp = blockIdx.x;   // 0..63 : (b,head,nh)
    int tid = threadIdx.x;  // 256
    int head = (grp >> 1) & 3;
    int b    =  grp >> 3;
    int bh   = b*NHEAD + head;

    float4 ca = make_float4(0,0,0,0);
    float4 cb4 = make_float4(0,0,0,0);
    for (int c = 0; c < NCHUNK; c++) {
        size_t base = ((size_t)(grp*16 + c)*256 + tid)*8;
        *(float4*)&g_carry[base]     = ca;
        *(float4*)&g_carry[base + 4] = cb4;
        int lend = (c+1)*CS < L_ ? (c+1)*CS : L_;
        float pf = g_cd[bh*L_ + lend - 1];
        float4 s0 = *(const float4*)&g_st[base];
        float4 s1 = *(const float4*)&g_st[base + 4];
        ca.x = fmaf(ca.x, pf, s0.x); ca.y = fmaf(ca.y, pf, s0.y);
        ca.z = fmaf(ca.z, pf, s0.z); ca.w = fmaf(ca.w, pf, s0.w);
        cb4.x = fmaf(cb4.x, pf, s1.x); cb4.y = fmaf(cb4.y, pf, s1.y);
        cb4.z = fmaf(cb4.z, pf, s1.z); cb4.w = fmaf(cb4.w, pf, s1.w);
    }
}

// ---------------- pass 3: correction y_t += P_t * (C_t . carry) -------------
__global__ void k_scan3(int layer)
{
    __shared__ float cs_s[SCHUNK][32];
    __shared__ float ps[SCHUNK];
    __shared__ float yp[SCHUNK*4*64];

    int blk   = blockIdx.x;
    int chunk = blk & 15;
    if (chunk == 0) return;               // zero carry, no correction
    int grp   = blk >> 4;
    int nh    =  grp       & 1;
    int head  = (grp >> 1) & 3;
    int b     =  grp >> 3;

    int c0   = chunk * CS;
    int cend = (c0 + CS < L_) ? (c0 + CS) : L_;

    int tid  = threadIdx.x;
    int w    = tid >> 5, lane = tid & 31;
    int p    = ((w & 1) << 5) + lane;
    int nchunk = w >> 1;

    float s[8];
    {
        size_t cbase = ((size_t)blk*256 + tid)*8;
        float4 s0 = *(const float4*)&g_carry[cbase];
        float4 s1 = *(const float4*)&g_carry[cbase + 4];
        s[0]=s0.x; s[1]=s0.y; s[2]=s0.z; s[3]=s0.w;
        s[4]=s1.x; s[5]=s1.y; s[6]=s1.z; s[7]=s1.w;
    }

    int cdb = (b*NHEAD + head)*L_;
    int lls = tid >> 4;
    int jj  = (tid & 15) * 2;
    int rls = tid >> 4;
    int rp4 = (tid & 15) << 2;
    float* ypbase = &g_yp[nh][0];

    for (int l0 = c0; l0 < cend; l0 += SCHUNK) {
        {
            int ll = l0 + lls;
            float2 v = make_float2(0.0f, 0.0f);
            if (ll < L_)
                v = *(const float2*)(g_xc + (size_t)(b*L_ + ll)*CD + 320 + nh*32 + jj);
            cs_s[lls][jj]     = v.x;
            cs_s[lls][jj + 1] = v.y;
            if (tid < SCHUNK) {
                int l2 = l0 + tid;
                ps[tid] = (l2 < L_) ? g_cd[cdb + l2] : 0.0f;
            }
        }
        __syncthreads();

        int smax = (cend - l0 < SCHUNK) ? (cend - l0) : SCHUNK;
        for (int ls = 0; ls < smax; ++ls) {
            const float* cc = &cs_s[ls][nchunk << 3];
            float4 cv0 = *(const float4*)cc, cv1 = *(const float4*)(cc + 4);
            float acc;
            acc = s[0]*cv0.x;
            acc = fmaf(s[1], cv0.y, acc);
            acc = fmaf(s[2], cv0.z, acc);
            acc = fmaf(s[3], cv0.w, acc);
            acc = fmaf(s[4], cv1.x, acc);
            acc = fmaf(s[5], cv1.y, acc);
            acc = fmaf(s[6], cv1.z, acc);
            acc = fmaf(s[7], cv1.w, acc);
            yp[((ls << 2) + nchunk)*64 + p] = acc * ps[ls];
        }
        __syncthreads();

        if (l0 + rls < cend) {
            const float* y0 = &yp[(rls << 2)*64 + rp4];
            float4 a0 = *(const float4*)(y0);
            float4 a1 = *(const float4*)(y0 + 64);
            float4 a2 = *(const float4*)(y0 + 128);
            float4 a3 = *(const float4*)(y0 + 192);
            float* dst = ypbase + (size_t)(b*L_ + l0 + rls)*DIN + head*64 + rp4;
            float4 old = *(const float4*)dst;
            float4 r;
            r.x = old.x + a0.x + a1.x + a2.x + a3.x;
            r.y = old.y + a0.y + a1.y + a2.y + a3.y;
            r.z = old.z + a0.z + a1.z + a2.z + a3.z;
            r.w = old.w + a0.w + a1.w + a2.w + a3.w;
            *(float4*)dst = r;
        }
        __syncthreads();
    }
}

// ---------------- y = (ysum + Dh*x) * silu(z); RMSNorm * norm_w -------------
__global__ void k_postscan(const float* __restrict__ Dh, const float* __restrict__ nw,
                           int layer)
{
    int row = blockIdx.x;
    int c = threadIdx.x;         // 256
    int head = c >> 6;
    size_t idx = (size_t)row*DIN + c;
    float xh = g_xc[(size_t)row*CD + c];
    float y  = g_yp[0][idx] + g_yp[1][idx] + Dh[layer*NHEAD + head]*xh;
    float z  = g_zx[(size_t)row*DPJ + c];
    y *= z / (1.0f + __expf(-z));

    float ss = y*y;
    #pragma unroll
    for (int o = 16; o > 0; o >>= 1) ss += __shfl_xor_sync(0xffffffffu, ss, o);
    __shared__ float part[8];
    if ((c & 31) == 0) part[c >> 5] = ss;
    __syncthreads();
    float tot = part[0]+part[1]+part[2]+part[3]+part[4]+part[5]+part[6]+part[7];
    float r = rsqrtf(tot*(1.0f/256.0f) + 1e-5f);
    g_y[idx] = y * r * nw[layer*DIN + c];
}

// ---------------- final head: LN(cls) @ head_w + head_b ---------------------
__global__ void k_head(const float* __restrict__ lnw, const float* __restrict__ lnb,
                       const float* __restrict__ hw,  const float* __restrict__ hb,
                       float* __restrict__ out)
{
    int b = blockIdx.x, t = threadIdx.x;   // 128
    __shared__ float part[4];
    float v = g_h[(size_t)(b*L_ + L_-1)*DIM + t];

    float ssum = v;
    #pragma unroll
    for (int o = 16; o > 0; o >>= 1) ssum += __shfl_xor_sync(0xffffffffu, ssum, o);
    if ((t & 31) == 0) part[t >> 5] = ssum;
    __syncthreads();
    float mu = (part[0]+part[1]+part[2]+part[3]) * (1.0f/128.0f);
    __syncthreads();

    float d = v - mu;
    float ss = d*d;
    #pragma unroll
    for (int o = 16; o > 0; o >>= 1) ss += __shfl_xor_sync(0xffffffffu, ss, o);
    if ((t & 31) == 0) part[t >> 5] = ss;
    __syncthreads();
    float var = (part[0]+part[1]+part[2]+part[3]) * (1.0f/128.0f);
    __syncthreads();

    float cn = d * rsqrtf(var + 1e-5f) * lnw[t] + lnb[t];
    float dd = cn * hw[t];
    #pragma unroll
    for (int o = 16; o > 0; o >>= 1) dd += __shfl_xor_sync(0xffffffffu, dd, o);
    if ((t & 31) == 0) part[t >> 5] = dd;
    __syncthreads();
    if (t == 0) out[b] = part[0]+part[1]+part[2]+part[3] + hb[0];
}

// ---------------- copy final hidden states into output ----------------------
__global__ void k_copyh(float* __restrict__ dst)
{
    size_t i = ((size_t)blockIdx.x*256 + threadIdx.x) * 4;
    *(float4*)(dst + i) = *(const float4*)(g_h + i);
}

// ---------------- launch ----------------------------------------------------
extern "C" void kernel_launch(void* const* d_in, const int* in_sizes, int n_in,
                              void* d_out, int out_size)
{
    const float* x      = (const float*)d_in[0];
    const float* w1     = (const float*)d_in[1];
    const float* b1     = (const float*)d_in[2];
    const float* w2     = (const float*)d_in[3];
    const float* b2     = (const float*)d_in[4];
    const float* cls    = (const float*)d_in[5];
    const float* inw    = (const float*)d_in[6];
    const float* cw     = (const float*)d_in[7];
    const float* cb     = (const float*)d_in[8];
    const float* dtb    = (const float*)d_in[9];
    const float* A_log  = (const float*)d_in[10];
    const float* Dh     = (const float*)d_in[11];
    const float* nw     = (const float*)d_in[12];
    const float* ow     = (const float*)d_in[13];
    const float* lnw    = (const float*)d_in[14];
    const float* lnb    = (const float*)d_in[15];
    const float* hw     = (const float*)d_in[16];
    const float* hb     = (const float*)d_in[17];
    float* out = (float*)d_out;

    float *ph, *pzx, *py;
    cudaGetSymbolAddress((void**)&ph,  g_h);
    cudaGetSymbolAddress((void**)&pzx, g_zx);
    cudaGetSymbolAddress((void**)&py,  g_y);

    k_frontend<<<dim3(256, B_), 128>>>(x, w1, b1, w2, b2, cls);

    for (int i = 0; i < DEPTH; i++) {
        k_gemm<<<dim3((NR+63)/64, (DPJ+63)/64), 256>>>(
            ph, inw + (size_t)i*DPJ*DIM, pzx, NR, DPJ, DIM);
        k_convdt<<<NR, 128>>>(cw, cb, dtb, i);
        // chunked scan: local pass, carry fix-up, correction pass
        k_scan1<<<1024, 256>>>(A_log, i);
        k_fix  <<<64, 256>>>(i);
        k_scan3<<<1024, 256>>>(i);
        k_postscan<<<NR, 256>>>(Dh, nw, i);
        k_gemm<<<dim3((NR+63)/64, (DIM+63)/64), 256>>>(
            py, ow + (size_t)i*DIM*DIN, ph, NR, DIM, DIN);
    }

    k_head<<<B_, 128>>>(lnw, lnb, hw, hb, out);
    k_copyh<<<L_, 256>>>(out + 8);
}

// round 17
// speedup vs baseline: 1.0031x; 1.0031x over previous
#include <cuda_runtime.h>
#include <math.h>

#define B_    8
#define T_    2048
#define L0_   2044          // conv-window output length
#define L_    2045          // after cls token
#define NR    (B_*L_)       // 16360 rows
#define DIM   128
#define DIN   256
#define NHEAD 4
#define PDIM  64
#define NSTATE 64
#define CD    384           // conv_dim
#define DPJ   644           // d_in_proj
#define DEPTH 4
#define SCHUNK 16
#define CS     128          // scan chunk size (sequential steps per block)
#define NCHUNK 16           // ceil(2045/128)

// ---------------- scratch (static device globals; no runtime allocation) -----
__device__ float g_h [NR*DIM];               // hidden (B,L,128)
__device__ float g_zx[(size_t)NR*DPJ];       // zxbcdt (B,L,644)
__device__ float g_xc[(size_t)NR*CD];        // conv+silu output (B,L,384)
__device__ float g_dt[NR*NHEAD];             // softplus(dt) (B,L,4)
__device__ float g_yp[2][(size_t)NR*DIN];    // y partials (2 n-halves)
__device__ float g_y [(size_t)NR*DIN];       // normalized y (B,L,256)
__device__ float g_cd[B_*NHEAD*L_];          // within-chunk cumulative decay P_t
__device__ float g_st[(size_t)1024*256*8];   // chunk-end states per scan1 block
__device__ float g_carry[(size_t)1024*256*8];// carry-in states per chunk

// ---------------- frontend: sliding window -> MLP -> h; also write cls row ---
__global__ void k_frontend(const float* __restrict__ x,
                           const float* __restrict__ w1, const float* __restrict__ b1,
                           const float* __restrict__ w2, const float* __restrict__ b2,
                           const float* __restrict__ cls)
{
    int b = blockIdx.y;
    int t = threadIdx.x;              // 128
    __shared__ float toks[16];
    __shared__ float h1s[128];

    if (blockIdx.x == 0) {
        g_h[(size_t)(b*L_ + (L_-1))*DIM + t] = cls[t];
    }
    for (int r = 0; r < 8; ++r) {
        int l = blockIdx.x*8 + r;
        if (l >= L0_) break;
        if (t < 15) toks[t] = x[(size_t)(b*T_ + l + t/3)*3 + (t%3)];
        __syncthreads();
        float a = b1[t];
        #pragma unroll
        for (int j = 0; j < 15; j++) a = fmaf(toks[j], w1[t*15 + j], a);
        a = 0.5f*a*(1.0f + erff(a*0.70710678118654752f));
        h1s[t] = a;
        __syncthreads();
        float o = b2[t];
        #pragma unroll 8
        for (int j = 0; j < 128; j++) o = fmaf(h1s[j], w2[t*128 + j], o);
        g_h[(size_t)(b*L_ + l)*DIM + t] = o;
        __syncthreads();
    }
}

// ---------------- generic SGEMM: C[M,N] = A[M,K] @ W[N,K]^T ------------------
__global__ void k_gemm(const float* __restrict__ A, const float* __restrict__ W,
                       float* __restrict__ C, int M, int N, int K)
{
    __shared__ float As[64][68];
    __shared__ float Bs[64][68];
    int tid = threadIdx.x;
    int tx = tid & 15, ty = tid >> 4;
    int bm = blockIdx.x * 64, bn = blockIdx.y * 64;
    float acc[4][4] = {};
    int lr = tid >> 2;
    int lk = (tid & 3) * 16;

    for (int kb = 0; kb < K; kb += 64) {
        {
            int gr = bm + lr;
            const float* ap = A + (size_t)gr*K + kb + lk;
            #pragma unroll
            for (int i = 0; i < 16; i += 4) {
                float4 v = (gr < M) ? *(const float4*)(ap + i) : make_float4(0,0,0,0);
                As[lk+i+0][lr] = v.x; As[lk+i+1][lr] = v.y;
                As[lk+i+2][lr] = v.z; As[lk+i+3][lr] = v.w;
            }
            int gc = bn + lr;
            const float* wp = W + (size_t)gc*K + kb + lk;
            #pragma unroll
            for (int i = 0; i < 16; i += 4) {
                float4 v = (gc < N) ? *(const float4*)(wp + i) : make_float4(0,0,0,0);
                Bs[lk+i+0][lr] = v.x; Bs[lk+i+1][lr] = v.y;
                Bs[lk+i+2][lr] = v.z; Bs[lk+i+3][lr] = v.w;
            }
        }
        __syncthreads();
        #pragma unroll 16
        for (int kk = 0; kk < 64; ++kk) {
            float4 a  = *(const float4*)&As[kk][ty*4];
            float4 bv = *(const float4*)&Bs[kk][tx*4];
            float av[4] = {a.x, a.y, a.z, a.w};
            float bw[4] = {bv.x, bv.y, bv.z, bv.w};
            #pragma unroll
            for (int i = 0; i < 4; i++)
                #pragma unroll
                for (int j = 0; j < 4; j++)
                    acc[i][j] = fmaf(av[i], bw[j], acc[i][j]);
        }
        __syncthreads();
    }
    #pragma unroll
    for (int i = 0; i < 4; i++) {
        int r = bm + ty*4 + i;
        if (r < M) {
            #pragma unroll
            for (int j = 0; j < 4; j++) {
                int c = bn + tx*4 + j;
                if (c < N) C[(size_t)r*N + c] = acc[i][j];
            }
        }
    }
}

// ---------------- causal depthwise conv (K=4) + SiLU, and softplus(dt) ------
__global__ void k_convdt(const float* __restrict__ cw, const float* __restrict__ cb,
                         const float* __restrict__ dtb, int layer)
{
    int row = blockIdx.x;
    int b = row / L_;
    int l = row - b*L_;
    int t = threadIdx.x;   // 128
    #pragma unroll
    for (int rep = 0; rep < 3; rep++) {
        int c = t + rep*128;
        float4 w = *(const float4*)(cw + ((size_t)layer*CD + c)*4);
        float wv[4] = {w.x, w.y, w.z, w.w};
        float acc = cb[layer*CD + c];
        #pragma unroll
        for (int k = 0; k < 4; k++) {
            int tt = l - 3 + k;
            if (tt >= 0)
                acc = fmaf(wv[k], g_zx[((size_t)(b*L_ + tt))*DPJ + DIN + c], acc);
        }
        acc = acc / (1.0f + __expf(-acc));   // SiLU
        g_xc[(size_t)row*CD + c] = acc;
    }
    if (t < NHEAD) {
        float raw = g_zx[(size_t)row*DPJ + 640 + t] + dtb[layer*NHEAD + t];
        float sp  = (raw > 20.0f) ? raw : log1pf(__expf(raw));
        g_dt[row*NHEAD + t] = sp;
    }
}

// ---------------- chunked SSM scan: pass 1 (local scan, h=0 start) ----------
// grid = 1024: blk = ((b*4+head)*2+nh)*16 + chunk. 256 threads:
//   warp w, lane l: p = (w&1)*32 + l ; nchunk = w>>2? no: w>>1 (8 n per thread)
__global__ void k_scan1(const float* __restrict__ A_log, int layer)
{
    __shared__ float in_s[SCHUNK][128];   // per step: x[64] | B[32] | C[32]
    __shared__ float dts[SCHUNK];
    __shared__ float yp[SCHUNK*4*64];     // [step][nchunk][p]

    int blk   = blockIdx.x;
    int chunk = blk & 15;
    int grp   = blk >> 4;                 // 0..63
    int nh    =  grp       & 1;
    int head  = (grp >> 1) & 3;
    int b     =  grp >> 3;
    float A   = -__expf(A_log[layer*NHEAD + head]);

    int c0   = chunk * CS;
    int cend = (c0 + CS < L_) ? (c0 + CS) : L_;

    int tid  = threadIdx.x;
    int w    = tid >> 5, lane = tid & 31;
    int p    = ((w & 1) << 5) + lane;
    int nchunk = w >> 1;

    float s[8];
    #pragma unroll
    for (int j = 0; j < 8; j++) s[j] = 0.0f;
    float cp = 1.0f;                      // cumulative decay within chunk
    int   cdb = (b*NHEAD + head)*L_;
    bool  wr_cd = (tid == 0) && (nh == 0);

    // cooperative-load mapping: 16 threads per step, 8 floats each
    int lls = tid >> 4;
    int j0  = (tid & 15) * 8;
    int goff;
    if (j0 < 64)      goff = head*64 + j0;
    else if (j0 < 96) goff = 256 + nh*32 + (j0 - 64);
    else              goff = 320 + nh*32 + (j0 - 96);

    int rls = tid >> 4;
    int rp4 = (tid & 15) << 2;
    float* ypbase = &g_yp[nh][0];

    for (int l0 = c0; l0 < cend; l0 += SCHUNK) {
        {
            int ll = l0 + lls;
            float4 v0, v1;
            if (ll < L_) {
                const float* rp = g_xc + (size_t)(b*L_ + ll)*CD + goff;
                v0 = *(const float4*)rp;
                v1 = *(const float4*)(rp + 4);
            } else {
                v0 = make_float4(0,0,0,0); v1 = v0;
            }
            *(float4*)&in_s[lls][j0]     = v0;
            *(float4*)&in_s[lls][j0 + 4] = v1;
            if (tid < SCHUNK) {
                int l2 = l0 + tid;
                dts[tid] = (l2 < L_) ? g_dt[(b*L_ + l2)*NHEAD + head] : 0.0f;
            }
        }
        __syncthreads();

        int smax = (cend - l0 < SCHUNK) ? (cend - l0) : SCHUNK;
        for (int ls = 0; ls < smax; ++ls) {
            float dtv   = dts[ls];
            float decay = __expf(dtv * A);
            cp *= decay;
            if (wr_cd) g_cd[cdb + l0 + ls] = cp;
            float dtx   = dtv * in_s[ls][p];
            const float* bp = &in_s[ls][64 + (nchunk << 3)];
            const float* cc = &in_s[ls][96 + (nchunk << 3)];
            float4 b0 = *(const float4*)bp,  b1 = *(const float4*)(bp + 4);
            float4 cv0 = *(const float4*)cc, cv1 = *(const float4*)(cc + 4);
            float acc;
            s[0] = fmaf(s[0], decay, dtx*b0.x); acc = s[0]*cv0.x;
            s[1] = fmaf(s[1], decay, dtx*b0.y); acc = fmaf(s[1], cv0.y, acc);
            s[2] = fmaf(s[2], decay, dtx*b0.z); acc = fmaf(s[2], cv0.z, acc);
            s[3] = fmaf(s[3], decay, dtx*b0.w); acc = fmaf(s[3], cv0.w, acc);
            s[4] = fmaf(s[4], decay, dtx*b1.x); acc = fmaf(s[4], cv1.x, acc);
            s[5] = fmaf(s[5], decay, dtx*b1.y); acc = fmaf(s[5], cv1.y, acc);
            s[6] = fmaf(s[6], decay, dtx*b1.z); acc = fmaf(s[6], cv1.z, acc);
            s[7] = fmaf(s[7], decay, dtx*b1.w); acc = fmaf(s[7], cv1.w, acc);
            yp[((ls << 2) + nchunk)*64 + p] = acc;
        }
        __syncthreads();

        if (l0 + rls < cend) {
            const float* y0 = &yp[(rls << 2)*64 + rp4];
            float4 a0 = *(const float4*)(y0);
            float4 a1 = *(const float4*)(y0 + 64);
            float4 a2 = *(const float4*)(y0 + 128);
            float4 a3 = *(const float4*)(y0 + 192);
            float4 r;
            r.x = a0.x + a1.x + a2.x + a3.x;
            r.y = a0.y + a1.y + a2.y + a3.y;
            r.z = a0.z + a1.z + a2.z + a3.z;
            r.w = a0.w + a1.w + a2.w + a3.w;
            *(float4*)(ypbase + (size_t)(b*L_ + l0 + rls)*DIN + head*64 + rp4) = r;
        }
        __syncthreads();
    }

    // store chunk-end state
    size_t sb = ((size_t)blk*256 + tid)*8;
    *(float4*)&g_st[sb]     = make_float4(s[0], s[1], s[2], s[3]);
    *(float4*)&g_st[sb + 4] = make_float4(s[4], s[5], s[6], s[7]);
}

// ---------------- pass 2: sequential chunk-carry fix-up (tiny) --------------
__global__ void k_fix(int layer)
{
    int grp = blockIdx.x;   // 0..63 : (b,head,nh)
    int tid = threadIdx.x;  // 256
    int head = (grp >> 1) & 3;
    int b    =  grp >> 3;
    int bh   = b*NHEAD + head;

    float4 ca = make_float4(0,0,0,0);
    float4 cb4 = make_float4(0,0,0,0);
    for (int c = 0; c < NCHUNK; c++) {
        size_t base = ((size_t)(grp*16 + c)*256 + tid)*8;
        *(float4*)&g_carry[base]     = ca;
        *(float4*)&g_carry[base + 4] = cb4;
        int lend = (c+1)*CS < L_ ? (c+1)*CS : L_;
        float pf = g_cd[bh*L_ + lend - 1];
        float4 s0 = *(const float4*)&g_st[base];
        float4 s1 = *(const float4*)&g_st[base + 4];
        ca.x = fmaf(ca.x, pf, s0.x); ca.y = fmaf(ca.y, pf, s0.y);
        ca.z = fmaf(ca.z, pf, s0.z); ca.w = fmaf(ca.w, pf, s0.w);
        cb4.x = fmaf(cb4.x, pf, s1.x); cb4.y = fmaf(cb4.y, pf, s1.y);
        cb4.z = fmaf(cb4.z, pf, s1.z); cb4.w = fmaf(cb4.w, pf, s1.w);
    }
}

// ---------------- pass 3: correction y_t += P_t * (C_t . carry) -------------
__global__ void k_scan3(int layer)
{
    __shared__ float cs_s[SCHUNK][32];
    __shared__ float ps[SCHUNK];
    __shared__ float yp[SCHUNK*4*64];

    int blk   = blockIdx.x;
    int chunk = blk & 15;
    if (chunk == 0) return;               // zero carry, no correction
    int grp   = blk >> 4;
    int nh    =  grp       & 1;
    int head  = (grp >> 1) & 3;
    int b     =  grp >> 3;

    int c0   = chunk * CS;
    int cend = (c0 + CS < L_) ? (c0 + CS) : L_;

    int tid  = threadIdx.x;
    int w    = tid >> 5, lane = tid & 31;
    int p    = ((w & 1) << 5) + lane;
    int nchunk = w >> 1;

    float s[8];
    {
        size_t cbase = ((size_t)blk*256 + tid)*8;
        float4 s0 = *(const float4*)&g_carry[cbase];
        float4 s1 = *(const float4*)&g_carry[cbase + 4];
        s[0]=s0.x; s[1]=s0.y; s[2]=s0.z; s[3]=s0.w;
        s[4]=s1.x; s[5]=s1.y; s[6]=s1.z; s[7]=s1.w;
    }

    int cdb = (b*NHEAD + head)*L_;
    int lls = tid >> 4;
    int jj  = (tid & 15) * 2;
    int rls = tid >> 4;
    int rp4 = (tid & 15) << 2;
    float* ypbase = &g_yp[nh][0];

    for (int l0 = c0; l0 < cend; l0 += SCHUNK) {
        {
            int ll = l0 + lls;
            float2 v = make_float2(0.0f, 0.0f);
            if (ll < L_)
                v = *(const float2*)(g_xc + (size_t)(b*L_ + ll)*CD + 320 + nh*32 + jj);
            cs_s[lls][jj]     = v.x;
            cs_s[lls][jj + 1] = v.y;
            if (tid < SCHUNK) {
                int l2 = l0 + tid;
                ps[tid] = (l2 < L_) ? g_cd[cdb + l2] : 0.0f;
            }
        }
        __syncthreads();

        int smax = (cend - l0 < SCHUNK) ? (cend - l0) : SCHUNK;
        for (int ls = 0; ls < smax; ++ls) {
            const float* cc = &cs_s[ls][nchunk << 3];
            float4 cv0 = *(const float4*)cc, cv1 = *(const float4*)(cc + 4);
            float acc;
            acc = s[0]*cv0.x;
            acc = fmaf(s[1], cv0.y, acc);
            acc = fmaf(s[2], cv0.z, acc);
            acc = fmaf(s[3], cv0.w, acc);
            acc = fmaf(s[4], cv1.x, acc);
            acc = fmaf(s[5], cv1.y, acc);
            acc = fmaf(s[6], cv1.z, acc);
            acc = fmaf(s[7], cv1.w, acc);
            yp[((ls << 2) + nchunk)*64 + p] = acc * ps[ls];
        }
        __syncthreads();

        if (l0 + rls < cend) {
            const float* y0 = &yp[(rls << 2)*64 + rp4];
            float4 a0 = *(const float4*)(y0);
            float4 a1 = *(const float4*)(y0 + 64);
            float4 a2 = *(const float4*)(y0 + 128);
            float4 a3 = *(const float4*)(y0 + 192);
            float* dst = ypbase + (size_t)(b*L_ + l0 + rls)*DIN + head*64 + rp4;
            float4 old = *(const float4*)dst;
            float4 r;
            r.x = old.x + a0.x + a1.x + a2.x + a3.x;
            r.y = old.y + a0.y + a1.y + a2.y + a3.y;
            r.z = old.z + a0.z + a1.z + a2.z + a3.z;
            r.w = old.w + a0.w + a1.w + a2.w + a3.w;
            *(float4*)dst = r;
        }
        __syncthreads();
    }
}

// ---------------- y = (ysum + Dh*x) * silu(z); RMSNorm * norm_w -------------
__global__ void k_postscan(const float* __restrict__ Dh, const float* __restrict__ nw,
                           int layer)
{
    int row = blockIdx.x;
    int c = threadIdx.x;         // 256
    int head = c >> 6;
    size_t idx = (size_t)row*DIN + c;
    float xh = g_xc[(size_t)row*CD + c];
    float y  = g_yp[0][idx] + g_yp[1][idx] + Dh[layer*NHEAD + head]*xh;
    float z  = g_zx[(size_t)row*DPJ + c];
    y *= z / (1.0f + __expf(-z));

    float ss = y*y;
    #pragma unroll
    for (int o = 16; o > 0; o >>= 1) ss += __shfl_xor_sync(0xffffffffu, ss, o);
    __shared__ float part[8];
    if ((c & 31) == 0) part[c >> 5] = ss;
    __syncthreads();
    float tot = part[0]+part[1]+part[2]+part[3]+part[4]+part[5]+part[6]+part[7];
    float r = rsqrtf(tot*(1.0f/256.0f) + 1e-5f);
    g_y[idx] = y * r * nw[layer*DIN + c];
}

// ---------------- final head: LN(cls) @ head_w + head_b ---------------------
__global__ void k_head(const float* __restrict__ lnw, const float* __restrict__ lnb,
                       const float* __restrict__ hw,  const float* __restrict__ hb,
                       float* __restrict__ out)
{
    int b = blockIdx.x, t = threadIdx.x;   // 128
    __shared__ float part[4];
    float v = g_h[(size_t)(b*L_ + L_-1)*DIM + t];

    float ssum = v;
    #pragma unroll
    for (int o = 16; o > 0; o >>= 1) ssum += __shfl_xor_sync(0xffffffffu, ssum, o);
    if ((t & 31) == 0) part[t >> 5] = ssum;
    __syncthreads();
    float mu = (part[0]+part[1]+part[2]+part[3]) * (1.0f/128.0f);
    __syncthreads();

    float d = v - mu;
    float ss = d*d;
    #pragma unroll
    for (int o = 16; o > 0; o >>= 1) ss += __shfl_xor_sync(0xffffffffu, ss, o);
    if ((t & 31) == 0) part[t >> 5] = ss;
    __syncthreads();
    float var = (part[0]+part[1]+part[2]+part[3]) * (1.0f/128.0f);
    __syncthreads();

    float cn = d * rsqrtf(var + 1e-5f) * lnw[t] + lnb[t];
    float dd = cn * hw[t];
    #pragma unroll
    for (int o = 16; o > 0; o >>= 1) dd += __shfl_xor_sync(0xffffffffu, dd, o);
    if ((t & 31) == 0) part[t >> 5] = dd;
    __syncthreads();
    if (t == 0) out[b] = part[0]+part[1]+part[2]+part[3] + hb[0];
}

// ---------------- copy final hidden states into output ----------------------
__global__ void k_copyh(float* __restrict__ dst)
{
    size_t i = ((size_t)blockIdx.x*256 + threadIdx.x) * 4;
    *(float4*)(dst + i) = *(const float4*)(g_h + i);
}

// ---------------- launch ----------------------------------------------------
extern "C" void kernel_launch(void* const* d_in, const int* in_sizes, int n_in,
                              void* d_out, int out_size)
{
    const float* x      = (const float*)d_in[0];
    const float* w1     = (const float*)d_in[1];
    const float* b1     = (const float*)d_in[2];
    const float* w2     = (const float*)d_in[3];
    const float* b2     = (const float*)d_in[4];
    const float* cls    = (const float*)d_in[5];
    const float* inw    = (const float*)d_in[6];
    const float* cw     = (const float*)d_in[7];
    const float* cb     = (const float*)d_in[8];
    const float* dtb    = (const float*)d_in[9];
    const float* A_log  = (const float*)d_in[10];
    const float* Dh     = (const float*)d_in[11];
    const float* nw     = (const float*)d_in[12];
    const float* ow     = (const float*)d_in[13];
    const float* lnw    = (const float*)d_in[14];
    const float* lnb    = (const float*)d_in[15];
    const float* hw     = (const float*)d_in[16];
    const float* hb     = (const float*)d_in[17];
    float* out = (float*)d_out;

    float *ph, *pzx, *py;
    cudaGetSymbolAddress((void**)&ph,  g_h);
    cudaGetSymbolAddress((void**)&pzx, g_zx);
    cudaGetSymbolAddress((void**)&py,  g_y);

    k_frontend<<<dim3(256, B_), 128>>>(x, w1, b1, w2, b2, cls);

    for (int i = 0; i < DEPTH; i++) {
        k_gemm<<<dim3((NR+63)/64, (DPJ+63)/64), 256>>>(
            ph, inw + (size_t)i*DPJ*DIM, pzx, NR, DPJ, DIM);
        k_convdt<<<NR, 128>>>(cw, cb, dtb, i);
        // chunked scan: local pass, carry fix-up, correction pass
        k_scan1<<<1024, 256>>>(A_log, i);
        k_fix  <<<64, 256>>>(i);
        k_scan3<<<1024, 256>>>(i);
        k_postscan<<<NR, 256>>>(Dh, nw, i);
        k_gemm<<<dim3((NR+63)/64, (DIM+63)/64), 256>>>(
            py, ow + (size_t)i*DIM*DIN, ph, NR, DIM, DIN);
    }

    k_head<<<B_, 128>>>(lnw, lnb, hw, hb, out);
    k_copyh<<<L_, 256>>>(out + 8);
}